// round 5
// baseline (speedup 1.0000x reference)
#include <cuda_runtime.h>
#include <math.h>

// ---------------- problem constants ----------------
#define BATCH 64
#define TSEQ  256
#define INDIM 264
#define SU    512
#define NH    4
#define MSZ   32
#define NA    256
#define DB    256
#define COMBD 904          // 264 + 512 + 128
#define OUTD  1192         // 256 + 512 + 424
#define UPDD  424
#define HP    106          // per-head interface params

// param offsets within a head: s(3) jd(1) j(3) gamma(1) erase(32) add(32) k(32) beta(1) g(1)
#define OFF_S     0
#define OFF_JD    3
#define OFF_J     4
#define OFF_GAM   7
#define OFF_ER    8
#define OFF_AD    40
#define OFF_K     72
#define OFF_BETA  104
#define OFF_G     105

#define EPSV 1e-12f

// ---------------- device-global scratch (no allocation) ----------------
__device__ float g_Wt[OUTD * COMBD];     // transposed packed weights: g_Wt[j][k]
__device__ float g_bias[OUTD];
__device__ float g_comb[BATCH * COMBD];
__device__ float g_state[BATCH * SU];
__device__ float g_upd[BATCH * UPDD];
__device__ float g_wt[BATCH * NH * NA];
__device__ float g_wtdyn[BATCH * NH * NA];
__device__ float g_mem[BATCH * MSZ * NA];

__device__ __forceinline__ float sigm(float x) { return 1.0f / (1.0f + expf(-x)); }
__device__ __forceinline__ float splus(float x) {
    return fmaxf(x, 0.0f) + log1pf(expf(-fabsf(x)));
}

// ---------------- weight repack: g_Wt[j][k] = W*[k][j], fused bias ----------------
__global__ void pack_kernel(const float* __restrict__ Wo, const float* __restrict__ bo,
                            const float* __restrict__ Ws, const float* __restrict__ bs,
                            const float* __restrict__ Wu, const float* __restrict__ bu) {
    int idx = blockIdx.x * 256 + threadIdx.x;
    if (idx < OUTD * COMBD) {
        int j = idx / COMBD;
        int k = idx - j * COMBD;
        float v;
        if (j < DB)            v = Wo[k * DB + j];
        else if (j < DB + SU)  v = Ws[k * SU + (j - DB)];
        else                   v = Wu[k * UPDD + (j - DB - SU)];
        g_Wt[idx] = v;
    }
    if (idx < OUTD) {
        g_bias[idx] = (idx < DB) ? bo[idx]
                    : (idx < DB + SU) ? bs[idx - DB]
                    : bu[idx - DB - SU];
    }
}

// ---------------- init: reset carry + build comb_0 ----------------
__global__ void init_kernel(const float* __restrict__ x) {
    int b = blockIdx.x, tid = threadIdx.x;
    for (int i = tid; i < SU; i += 256) g_state[b * SU + i] = 1.0f;
    for (int i = tid; i < NH * NA; i += 256) {
        float v = ((i & (NA - 1)) == 0) ? 1.0f : 0.0f;  // one-hot at address 0
        g_wt[b * NH * NA + i]    = v;
        g_wtdyn[b * NH * NA + i] = v;
    }
    for (int i = tid; i < MSZ * NA; i += 256) g_mem[b * MSZ * NA + i] = 0.01f;
    // comb_0 = [x_0, ones(512), read_0];  read_0[h][m] = mem0[m][0] = 0.01
    for (int i = tid; i < COMBD; i += 256) {
        float v;
        if (i < INDIM)            v = x[((size_t)b * TSEQ + 0) * INDIM + i];
        else if (i < INDIM + SU)  v = 1.0f;
        else                      v = 0.01f;
        g_comb[b * COMBD + i] = v;
    }
}

// ---------------- GEMM: raw = comb @ Wt + bias; nonlinearity; route ----------------
// grid = 149 CTAs (8 output cols each), 256 threads.
// warp w -> col j0+w; lane l -> rows l and l+32.
__global__ void __launch_bounds__(256) gemm_kernel(float* __restrict__ dout, int t) {
    __shared__ float cS[64][132];   // comb rows, padded: 132%4==0 -> LDS.128 aligned, conflict-free
    __shared__ float wT[8][132];    // per-column W rows (broadcast reads)

    int tid  = threadIdx.x;
    int warp = tid >> 5, lane = tid & 31;
    int j0 = blockIdx.x * 8;
    int j  = j0 + warp;

    float acc0 = 0.0f, acc1 = 0.0f;

    for (int k0 = 0; k0 < COMBD; k0 += 128) {
        int kc  = min(128, COMBD - k0);
        int kc4 = kc >> 2;
        // stage comb[64][kc] (coalesced float4 global reads, conflict-free STS)
        for (int i = tid; i < 64 * kc4; i += 256) {
            int b = i / kc4, kq = i - b * kc4;
            float4 v = *(const float4*)&g_comb[b * COMBD + k0 + kq * 4];
            *(float4*)&cS[b][kq * 4] = v;
        }
        // stage W[8 cols][kc]
        for (int i = tid; i < 8 * kc4; i += 256) {
            int c = i / kc4, kq = i - c * kc4;
            float4 v = *(const float4*)&g_Wt[(size_t)(j0 + c) * COMBD + k0 + kq * 4];
            *(float4*)&wT[c][kq * 4] = v;
        }
        __syncthreads();
        #pragma unroll 4
        for (int kk = 0; kk < kc; kk += 4) {
            float4 wv = *(const float4*)&wT[warp][kk];     // warp-broadcast
            float4 a  = *(const float4*)&cS[lane][kk];     // conflict-free LDS.128
            float4 bq = *(const float4*)&cS[lane + 32][kk];
            acc0 = fmaf(a.x,  wv.x, acc0); acc0 = fmaf(a.y,  wv.y, acc0);
            acc0 = fmaf(a.z,  wv.z, acc0); acc0 = fmaf(a.w,  wv.w, acc0);
            acc1 = fmaf(bq.x, wv.x, acc1); acc1 = fmaf(bq.y, wv.y, acc1);
            acc1 = fmaf(bq.z, wv.z, acc1); acc1 = fmaf(bq.w, wv.w, acc1);
        }
        __syncthreads();
    }

    float bias = g_bias[j];
    acc0 += bias; acc1 += bias;

    int r0 = lane, r1 = lane + 32;
    if (j < DB) {
        dout[((size_t)r0 * TSEQ + t) * DB + j] = sigm(acc0);
        dout[((size_t)r1 * TSEQ + t) * DB + j] = sigm(acc1);
    } else if (j < DB + SU) {
        g_state[r0 * SU + (j - DB)] = sigm(acc0);
        g_state[r1 * SU + (j - DB)] = sigm(acc1);
    } else {
        g_upd[r0 * UPDD + (j - DB - SU)] = acc0;
        g_upd[r1 * UPDD + (j - DB - SU)] = acc1;
    }
}

// ---------------- block reductions (256 threads) ----------------
__device__ __forceinline__ float blockSum(float v, float* red) {
    #pragma unroll
    for (int o = 16; o; o >>= 1) v += __shfl_xor_sync(0xffffffffu, v, o);
    int w = threadIdx.x >> 5;
    if ((threadIdx.x & 31) == 0) red[w] = v;
    __syncthreads();
    if (threadIdx.x < 8) {
        float r = red[threadIdx.x];
        #pragma unroll
        for (int o = 4; o; o >>= 1) r += __shfl_xor_sync(0xffu, r, o, 8);
        if (threadIdx.x == 0) red[32] = r;
    }
    __syncthreads();
    float res = red[32];
    __syncthreads();
    return res;
}

__device__ __forceinline__ float blockMax(float v, float* red) {
    #pragma unroll
    for (int o = 16; o; o >>= 1) v = fmaxf(v, __shfl_xor_sync(0xffffffffu, v, o));
    int w = threadIdx.x >> 5;
    if ((threadIdx.x & 31) == 0) red[w] = v;
    __syncthreads();
    if (threadIdx.x < 8) {
        float r = red[threadIdx.x];
        #pragma unroll
        for (int o = 4; o; o >>= 1) r = fmaxf(r, __shfl_xor_sync(0xffu, r, o, 8));
        if (threadIdx.x == 0) red[32] = r;
    }
    __syncthreads();
    float res = red[32];
    __syncthreads();
    return res;
}

// ---------------- per-batch memory/addressing update ----------------
// grid = 64 (one CTA per batch element), 256 threads (thread owns address n = tid).
__global__ void __launch_bounds__(256) update_kernel(const float* __restrict__ x, int t) {
    __shared__ float memS[MSZ][NA + 1];   // pad 257 -> conflict-free row AND column access
    __shared__ float wtS[NH][NA];
    __shared__ float wgS[NH][NA];
    __shared__ float upS[UPDD];
    __shared__ float pErase[NH][MSZ], pAdd[NH][MSZ], pK[NH][MSZ];
    __shared__ float pS[NH][3], pJ[NH][3];
    __shared__ float pJd[NH], pGam[NH], pBeta[NH], pG[NH];
    __shared__ float normInv[NA];
    __shared__ float readS[NH * MSZ];
    __shared__ float red[33];

    int b = blockIdx.x, tid = threadIdx.x;
    int n = tid;

    // ---- load state ----
    for (int i = tid; i < UPDD; i += 256)    upS[i] = g_upd[b * UPDD + i];
    for (int i = tid; i < NH * NA; i += 256) wtS[i >> 8][i & 255] = g_wt[b * NH * NA + i];
    for (int i = tid; i < MSZ * NA; i += 256) memS[i >> 8][i & 255] = g_mem[b * MSZ * NA + i];
    __syncthreads();

    // ---- parse interface params (4 heads x 32 lanes) ----
    if (tid < NH * 32) {
        int h = tid >> 5, lane = tid & 31;
        const float* up = &upS[h * HP];
        pErase[h][lane] = sigm(up[OFF_ER + lane]);
        pAdd[h][lane]   = up[OFF_AD + lane];
        float kt = tanhf(up[OFF_K + lane]);
        float ss = kt * kt;
        #pragma unroll
        for (int o = 16; o; o >>= 1) ss += __shfl_xor_sync(0xffffffffu, ss, o);
        pK[h][lane] = kt / (sqrtf(ss) + EPSV);
        if (lane == 0) {
            // shift softmax(softplus)
            float s0 = splus(up[OFF_S + 0]), s1 = splus(up[OFF_S + 1]), s2 = splus(up[OFF_S + 2]);
            float mx = fmaxf(s0, fmaxf(s1, s2));
            float e0 = expf(s0 - mx), e1 = expf(s1 - mx), e2 = expf(s2 - mx);
            float inv = 1.0f / (e0 + e1 + e2);
            pS[h][0] = e0 * inv; pS[h][1] = e1 * inv; pS[h][2] = e2 * inv;
            // 3-way jump softmax
            float j0r = up[OFF_J + 0], j1r = up[OFF_J + 1], j2r = up[OFF_J + 2];
            float jm = fmaxf(j0r, fmaxf(j1r, j2r));
            float f0 = expf(j0r - jm), f1 = expf(j1r - jm), f2 = expf(j2r - jm);
            float jinv = 1.0f / (f0 + f1 + f2);
            pJ[h][0] = f0 * jinv; pJ[h][1] = f1 * jinv; pJ[h][2] = f2 * jinv;
            pJd[h]   = sigm(up[OFF_JD]);
            pGam[h]  = 1.0f + splus(up[OFF_GAM]);
            pBeta[h] = splus(up[OFF_BETA]);
            pG[h]    = sigm(up[OFF_G]);
        }
    }
    __syncthreads();

    // ---- memory write (erase then add), using previous wt ----
    for (int idx = tid; idx < MSZ * NA; idx += 256) {
        int m = idx >> 8, nn = idx & 255;
        float val = memS[m][nn];
        float prod = 1.0f, addv = 0.0f;
        #pragma unroll
        for (int h = 0; h < NH; h++) {
            float w = wtS[h][nn];
            prod *= (1.0f - pErase[h][m] * w);
            addv = fmaf(pAdd[h][m], w, addv);
        }
        memS[m][nn] = val * prod + addv;
    }
    __syncthreads();

    // write memory back (next step's update reads it)
    for (int i = tid; i < MSZ * NA; i += 256)
        g_mem[b * MSZ * NA + i] = memS[i >> 8][i & 255];

    // ---- column norms of updated memory ----
    {
        float ss = 0.0f;
        #pragma unroll
        for (int m = 0; m < MSZ; m++) { float v = memS[m][n]; ss = fmaf(v, v, ss); }
        normInv[n] = 1.0f / (sqrtf(ss) + EPSV);
    }
    __syncthreads();

    // ---- content addressing: softmax(beta * cos), interpolation gate ----
    for (int h = 0; h < NH; h++) {
        float sc = 0.0f;
        #pragma unroll
        for (int m = 0; m < MSZ; m++) sc = fmaf(pK[h][m], memS[m][n], sc);
        sc *= pBeta[h] * normInv[n];
        float mx = blockMax(sc, red);
        float e  = expf(sc - mx);
        float sm = blockSum(e, red);
        float wc = e / sm;
        float g  = pG[h];
        wgS[h][n] = g * wc + (1.0f - g) * wtS[h][n];
    }
    __syncthreads();

    // ---- shift, sharpen, snapshot, jump ----
    for (int h = 0; h < NH; h++) {
        float xm1 = wgS[h][(n + NA - 1) & (NA - 1)];
        float x0  = wgS[h][n];
        float xp1 = wgS[h][(n + 1) & (NA - 1)];
        float ws = pS[h][0] * xm1 + pS[h][1] * x0 + pS[h][2] * xp1;
        ws = powf(ws + EPSV, pGam[h]);
        float sm = blockSum(ws, red);
        ws /= sm;
        int gi = b * NH * NA + h * NA + n;
        float dynOld = g_wtdyn[gi];
        float jd = pJd[h];
        float dynNew = (1.0f - jd) * dynOld + jd * ws;
        g_wtdyn[gi] = dynNew;
        float wnew = pJ[h][0] * ws + pJ[h][1] * dynNew + ((n == 0) ? pJ[h][2] : 0.0f);
        g_wt[gi] = wnew;
        wtS[h][n] = wnew;   // reuse for the read below
    }
    __syncthreads();

    // ---- read for next step: read[h][m] = sum_n wt_new[h][n] * mem[m][n] ----
    if (tid < NH * MSZ) {
        int h = tid >> 5, m = tid & 31;
        float acc = 0.0f;
        for (int nn = 0; nn < NA; nn++)
            acc = fmaf(wtS[h][nn], memS[m][nn], acc);   // memS column: pad 257 -> conflict-free
        readS[tid] = acc;
    }
    __syncthreads();

    // ---- assemble comb_{t+1} = [x_{t+1}, state, read] ----
    for (int i = tid; i < COMBD; i += 256) {
        float v;
        if (i < INDIM)            v = x[((size_t)b * TSEQ + (t + 1)) * INDIM + i];
        else if (i < INDIM + SU)  v = g_state[b * SU + (i - INDIM)];
        else                      v = readS[i - INDIM - SU];
        g_comb[b * COMBD + i] = v;
    }
}

// ---------------- host ----------------
extern "C" void kernel_launch(void* const* d_in, const int* in_sizes, int n_in,
                              void* d_out, int out_size) {
    const float* x  = (const float*)d_in[0];
    const float* Wo = (const float*)d_in[1];
    const float* bo = (const float*)d_in[2];
    const float* Ws = (const float*)d_in[3];
    const float* bs = (const float*)d_in[4];
    const float* Wu = (const float*)d_in[5];
    const float* bu = (const float*)d_in[6];
    float* out = (float*)d_out;

    pack_kernel<<<(OUTD * COMBD + 255) / 256, 256>>>(Wo, bo, Ws, bs, Wu, bu);
    init_kernel<<<BATCH, 256>>>(x);
    for (int t = 0; t < TSEQ; t++) {
        gemm_kernel<<<OUTD / 8, 256>>>(out, t);
        if (t < TSEQ - 1) update_kernel<<<BATCH, 256>>>(x, t);
    }
}

// round 6
// speedup vs baseline: 2.0030x; 2.0030x over previous
#include <cuda_runtime.h>
#include <math.h>

// ---------------- problem constants ----------------
#define BATCH 64
#define TSEQ  256
#define INDIM 264
#define SU    512
#define NH    4
#define MSZ   32
#define NA    256
#define DB    256
#define COMBD 904          // 264 + 512 + 128
#define COMBP 1024         // padded K (zeros in [904,1024))
#define OUTD  1192         // 256 + 512 + 424
#define UPDD  424
#define HP    106          // per-head interface params

// param offsets within a head: s(3) jd(1) j(3) gamma(1) erase(32) add(32) k(32) beta(1) g(1)
#define OFF_S     0
#define OFF_JD    3
#define OFF_J     4
#define OFF_GAM   7
#define OFF_ER    8
#define OFF_AD    40
#define OFF_K     72
#define OFF_BETA  104
#define OFF_G     105

#define EPSV 1e-12f

// ---------------- device-global scratch (no allocation) ----------------
__device__ float g_Wt[OUTD * COMBP];     // transposed packed weights: g_Wt[j][k], K padded
__device__ float g_bias[OUTD];
__device__ float g_comb[BATCH * COMBP];  // K padded with zeros
__device__ float g_state[BATCH * SU];
__device__ float g_upd[BATCH * UPDD];
__device__ float g_wt[BATCH * NH * NA];
__device__ float g_wtdyn[BATCH * NH * NA];
__device__ float g_mem[BATCH * MSZ * NA];

__device__ __forceinline__ float sigm(float x) { return 1.0f / (1.0f + __expf(-x)); }
__device__ __forceinline__ float splus(float x) {
    return fmaxf(x, 0.0f) + log1pf(__expf(-fabsf(x)));
}

// ---------------- weight repack: g_Wt[j][k] = W*[k][j], zero pad, fused bias ----------------
__global__ void pack_kernel(const float* __restrict__ Wo, const float* __restrict__ bo,
                            const float* __restrict__ Ws, const float* __restrict__ bs,
                            const float* __restrict__ Wu, const float* __restrict__ bu) {
    int idx = blockIdx.x * 256 + threadIdx.x;
    if (idx < OUTD * COMBP) {
        int j = idx >> 10;          // / COMBP
        int k = idx & (COMBP - 1);  // % COMBP
        float v = 0.0f;
        if (k < COMBD) {
            if (j < DB)            v = Wo[k * DB + j];
            else if (j < DB + SU)  v = Ws[k * SU + (j - DB)];
            else                   v = Wu[k * UPDD + (j - DB - SU)];
        }
        g_Wt[idx] = v;
    }
    if (idx < OUTD) {
        g_bias[idx] = (idx < DB) ? bo[idx]
                    : (idx < DB + SU) ? bs[idx - DB]
                    : bu[idx - DB - SU];
    }
}

// ---------------- init: reset carry + build comb_0 ----------------
__global__ void init_kernel(const float* __restrict__ x) {
    int b = blockIdx.x, tid = threadIdx.x;
    for (int i = tid; i < SU; i += 256) g_state[b * SU + i] = 1.0f;
    for (int i = tid; i < NH * NA; i += 256) {
        float v = ((i & (NA - 1)) == 0) ? 1.0f : 0.0f;  // one-hot at address 0
        g_wt[b * NH * NA + i]    = v;
        g_wtdyn[b * NH * NA + i] = v;
    }
    for (int i = tid; i < MSZ * NA; i += 256) g_mem[b * MSZ * NA + i] = 0.01f;
    // comb_0 = [x_0, ones(512), read_0, zero-pad];  read_0[h][m] = mem0[m][0] = 0.01
    for (int i = tid; i < COMBP; i += 256) {
        float v;
        if (i < INDIM)            v = x[((size_t)b * TSEQ + 0) * INDIM + i];
        else if (i < INDIM + SU)  v = 1.0f;
        else if (i < COMBD)       v = 0.01f;
        else                      v = 0.0f;
        g_comb[b * COMBP + i] = v;
    }
}

// ---------------- GEMM: raw = comb @ Wt + bias; nonlinearity; route ----------------
// grid = 149 CTAs (8 output cols each), 256 threads.
// warp w -> col j0+w; lane l -> rows l and l+32. Register-prefetch double buffering.
__global__ void __launch_bounds__(256) gemm_kernel(float* __restrict__ dout, int t) {
    __shared__ float cS[64][132];   // 132 ≡ 4 (mod 32) -> conflict-free LDS.128
    __shared__ float wS[8][132];

    int tid  = threadIdx.x;
    int warp = tid >> 5, lane = tid & 31;
    int j0 = blockIdx.x * 8;
    int j  = j0 + warp;

    float4 cP[8];
    float4 wP;

    // prefetch chunk 0
    #pragma unroll
    for (int s = 0; s < 8; s++) {
        int p = tid + s * 256;          // 2048 float4 per chunk
        int bi = p >> 5, kq = p & 31;
        cP[s] = *(const float4*)&g_comb[bi * COMBP + kq * 4];
    }
    wP = *(const float4*)&g_Wt[(size_t)j * COMBP + lane * 4];

    float a00 = 0.f, a01 = 0.f, a10 = 0.f, a11 = 0.f;

    #pragma unroll 1
    for (int c = 0; c < 8; c++) {
        // commit prefetched chunk to smem
        #pragma unroll
        for (int s = 0; s < 8; s++) {
            int p = tid + s * 256;
            int bi = p >> 5, kq = p & 31;
            *(float4*)&cS[bi][kq * 4] = cP[s];
        }
        *(float4*)&wS[warp][lane * 4] = wP;
        __syncthreads();

        // prefetch next chunk (overlaps with compute below)
        if (c < 7) {
            int k0n = (c + 1) * 128;
            #pragma unroll
            for (int s = 0; s < 8; s++) {
                int p = tid + s * 256;
                int bi = p >> 5, kq = p & 31;
                cP[s] = *(const float4*)&g_comb[bi * COMBP + k0n + kq * 4];
            }
            wP = *(const float4*)&g_Wt[(size_t)j * COMBP + k0n + lane * 4];
        }

        #pragma unroll 8
        for (int kk = 0; kk < 128; kk += 4) {
            float4 wv = *(const float4*)&wS[warp][kk];      // broadcast
            float4 av = *(const float4*)&cS[lane][kk];
            float4 bv = *(const float4*)&cS[lane + 32][kk];
            a00 = fmaf(av.x, wv.x, a00); a01 = fmaf(av.y, wv.y, a01);
            a00 = fmaf(av.z, wv.z, a00); a01 = fmaf(av.w, wv.w, a01);
            a10 = fmaf(bv.x, wv.x, a10); a11 = fmaf(bv.y, wv.y, a11);
            a10 = fmaf(bv.z, wv.z, a10); a11 = fmaf(bv.w, wv.w, a11);
        }
        __syncthreads();
    }

    float bias = g_bias[j];
    float acc0 = a00 + a01 + bias;
    float acc1 = a10 + a11 + bias;

    int r0 = lane, r1 = lane + 32;
    if (j < DB) {
        dout[((size_t)r0 * TSEQ + t) * DB + j] = sigm(acc0);
        dout[((size_t)r1 * TSEQ + t) * DB + j] = sigm(acc1);
    } else if (j < DB + SU) {
        g_state[r0 * SU + (j - DB)] = sigm(acc0);
        g_state[r1 * SU + (j - DB)] = sigm(acc1);
    } else {
        g_upd[r0 * UPDD + (j - DB - SU)] = acc0;
        g_upd[r1 * UPDD + (j - DB - SU)] = acc1;
    }
}

// ---------------- per-batch memory/addressing update ----------------
// grid = 64 (one CTA per batch element), 1024 threads: thread = (head h, address n).
__global__ void __launch_bounds__(1024) update_kernel(const float* __restrict__ x, int t) {
    __shared__ float memS[MSZ][NA + 1];   // 257 stride -> conflict-free row & column access
    __shared__ float wtS[NH][NA];
    __shared__ float wgS[NH][NA];
    __shared__ float upS[UPDD];
    __shared__ float pErase[NH][MSZ], pAdd[NH][MSZ], pK[NH][MSZ];
    __shared__ float pS[NH][3], pJ[NH][3];
    __shared__ float pJd[NH], pGam[NH], pBeta[NH], pG[NH];
    __shared__ float readS[NH * MSZ];
    __shared__ float redA[NH][8], redB[NH][8];

    int b   = blockIdx.x, tid = threadIdx.x;
    int h   = tid >> 8;          // head
    int n   = tid & 255;         // address
    int wih = (tid >> 5) & 7;    // warp index within head
    int lane = tid & 31;

    // ---- load carry state ----
    if (tid < UPDD) upS[tid] = g_upd[b * UPDD + tid];
    wtS[h][n] = g_wt[b * NH * NA + tid];
    #pragma unroll
    for (int r = 0; r < 8; r++) {
        int i = tid + r * 1024;
        memS[i >> 8][i & 255] = g_mem[b * MSZ * NA + i];
    }
    __syncthreads();

    // ---- parse interface params (4 heads x 32 lanes) ----
    if (tid < NH * 32) {
        int hh = tid >> 5, m = tid & 31;
        const float* up = &upS[hh * HP];
        pErase[hh][m] = sigm(up[OFF_ER + m]);
        pAdd[hh][m]   = up[OFF_AD + m];
        float kt = tanhf(up[OFF_K + m]);
        float ssk = kt * kt;
        #pragma unroll
        for (int o = 16; o; o >>= 1) ssk += __shfl_xor_sync(0xffffffffu, ssk, o);
        pK[hh][m] = kt / (sqrtf(ssk) + EPSV);
        if (m == 0) {
            float s0 = splus(up[OFF_S + 0]), s1 = splus(up[OFF_S + 1]), s2 = splus(up[OFF_S + 2]);
            float mx = fmaxf(s0, fmaxf(s1, s2));
            float e0 = __expf(s0 - mx), e1 = __expf(s1 - mx), e2 = __expf(s2 - mx);
            float inv = 1.0f / (e0 + e1 + e2);
            pS[hh][0] = e0 * inv; pS[hh][1] = e1 * inv; pS[hh][2] = e2 * inv;
            float j0r = up[OFF_J + 0], j1r = up[OFF_J + 1], j2r = up[OFF_J + 2];
            float jm = fmaxf(j0r, fmaxf(j1r, j2r));
            float f0 = __expf(j0r - jm), f1 = __expf(j1r - jm), f2 = __expf(j2r - jm);
            float jinv = 1.0f / (f0 + f1 + f2);
            pJ[hh][0] = f0 * jinv; pJ[hh][1] = f1 * jinv; pJ[hh][2] = f2 * jinv;
            pJd[hh]   = sigm(up[OFF_JD]);
            pGam[hh]  = 1.0f + splus(up[OFF_GAM]);
            pBeta[hh] = splus(up[OFF_BETA]);
            pG[hh]    = sigm(up[OFF_G]);
        }
    }
    __syncthreads();

    // ---- memory write (erase then add) with previous wt; write back to global ----
    #pragma unroll
    for (int r = 0; r < 8; r++) {
        int i = tid + r * 1024;
        int m = i >> 8, nn = i & 255;
        float val = memS[m][nn];
        float prod = 1.0f, addv = 0.0f;
        #pragma unroll
        for (int hh = 0; hh < NH; hh++) {
            float w = wtS[hh][nn];
            prod *= (1.0f - pErase[hh][m] * w);
            addv = fmaf(pAdd[hh][m], w, addv);
        }
        val = val * prod + addv;
        memS[m][nn] = val;
        g_mem[b * MSZ * NA + i] = val;
    }
    __syncthreads();

    // ---- fused column norm + content score for (h, n) ----
    float ss = 0.0f, sc = 0.0f;
    #pragma unroll
    for (int m = 0; m < MSZ; m++) {
        float v = memS[m][n];
        ss = fmaf(v, v, ss);
        sc = fmaf(pK[h][m], v, sc);
    }
    sc = sc * pBeta[h] / (sqrtf(ss) + EPSV);

    // ---- per-head softmax (segmented block reduce: max then sum) ----
    float mv = sc;
    #pragma unroll
    for (int o = 16; o; o >>= 1) mv = fmaxf(mv, __shfl_xor_sync(0xffffffffu, mv, o));
    if (lane == 0) redA[h][wih] = mv;
    __syncthreads();
    mv = redA[h][0];
    #pragma unroll
    for (int w = 1; w < 8; w++) mv = fmaxf(mv, redA[h][w]);
    float e = __expf(sc - mv);
    float sv = e;
    #pragma unroll
    for (int o = 16; o; o >>= 1) sv += __shfl_xor_sync(0xffffffffu, sv, o);
    if (lane == 0) redB[h][wih] = sv;
    __syncthreads();
    float tot = redB[h][0];
    #pragma unroll
    for (int w = 1; w < 8; w++) tot += redB[h][w];
    float wc = e / tot;
    float g = pG[h];
    wgS[h][n] = fmaf(g, wc - wtS[h][n], wtS[h][n]);   // g*wc + (1-g)*wt
    __syncthreads();

    // ---- shift (circular conv, S=3), sharpen, snapshot, jump ----
    float ws = pS[h][0] * wgS[h][(n + NA - 1) & (NA - 1)]
             + pS[h][1] * wgS[h][n]
             + pS[h][2] * wgS[h][(n + 1) & (NA - 1)];
    ws = powf(ws + EPSV, pGam[h]);
    float sv2 = ws;
    #pragma unroll
    for (int o = 16; o; o >>= 1) sv2 += __shfl_xor_sync(0xffffffffu, sv2, o);
    if (lane == 0) redA[h][wih] = sv2;
    __syncthreads();
    float tot2 = redA[h][0];
    #pragma unroll
    for (int w = 1; w < 8; w++) tot2 += redA[h][w];
    ws /= tot2;

    int gi = b * NH * NA + tid;
    float jd = pJd[h];
    float dynNew = fmaf(jd, ws - g_wtdyn[gi], g_wtdyn[gi]);
    g_wtdyn[gi] = dynNew;
    float wnew = pJ[h][0] * ws + pJ[h][1] * dynNew + ((n == 0) ? pJ[h][2] : 0.0f);
    g_wt[gi] = wnew;
    wtS[h][n] = wnew;
    __syncthreads();

    // ---- read for next step: read[h][m] = sum_n wt_new[h][n] * mem[m][n] ----
    // 512 threads: (h, m, quarter q); bank-rotated inner index (m + 8q covers 32 banks)
    if (tid < 512) {
        int hh = tid >> 7;
        int m  = (tid >> 2) & 31;
        int q  = tid & 3;
        float acc = 0.0f;
        #pragma unroll
        for (int i = 0; i < 64; i++) {
            int nn = q * 64 + ((i + 8 * q) & 63);
            acc = fmaf(wtS[hh][nn], memS[m][nn], acc);
        }
        acc += __shfl_down_sync(0xffffffffu, acc, 2, 4);
        acc += __shfl_down_sync(0xffffffffu, acc, 1, 4);
        if (q == 0) readS[hh * MSZ + m] = acc;
    }
    __syncthreads();

    // ---- assemble comb_{t+1} = [x_{t+1}, state, read] (pad untouched, zero from init) ----
    if (tid < COMBD) {
        float v;
        if (tid < INDIM)            v = x[((size_t)b * TSEQ + (t + 1)) * INDIM + tid];
        else if (tid < INDIM + SU)  v = g_state[b * SU + (tid - INDIM)];
        else                        v = readS[tid - INDIM - SU];
        g_comb[b * COMBP + tid] = v;
    }
}

// ---------------- host ----------------
extern "C" void kernel_launch(void* const* d_in, const int* in_sizes, int n_in,
                              void* d_out, int out_size) {
    const float* x  = (const float*)d_in[0];
    const float* Wo = (const float*)d_in[1];
    const float* bo = (const float*)d_in[2];
    const float* Ws = (const float*)d_in[3];
    const float* bs = (const float*)d_in[4];
    const float* Wu = (const float*)d_in[5];
    const float* bu = (const float*)d_in[6];
    float* out = (float*)d_out;

    pack_kernel<<<(OUTD * COMBP + 255) / 256, 256>>>(Wo, bo, Ws, bs, Wu, bu);
    init_kernel<<<BATCH, 256>>>(x);
    for (int t = 0; t < TSEQ; t++) {
        gemm_kernel<<<OUTD / 8, 256>>>(out, t);
        if (t < TSEQ - 1) update_kernel<<<BATCH, 1024>>>(x, t);
    }
}

// round 7
// speedup vs baseline: 3.0446x; 1.5200x over previous
#include <cuda_runtime.h>
#include <math.h>

// ---------------- problem constants ----------------
#define BATCH 64
#define TSEQ  256
#define INDIM 264
#define SU    512
#define NH    4
#define MSZ   32
#define NA    256
#define DB    256
#define COMBD 904          // 264 + 512 + 128
#define COMBP 1024         // padded K
#define OUTD  1192
#define UPDD  424
#define HP    106

// gemm tiling
#define KSPLIT 4
#define KCH    256         // K per split
#define KSUB   64          // smem subchunk
#define CB     32          // cols per CTA
#define NCB    38          // ceil(1192/32)
#define PARTW  1216        // NCB*CB (padded col width)

// param offsets within a head: s(3) jd(1) j(3) gamma(1) erase(32) add(32) k(32) beta(1) g(1)
#define OFF_S     0
#define OFF_JD    3
#define OFF_J     4
#define OFF_GAM   7
#define OFF_ER    8
#define OFF_AD    40
#define OFF_K     72
#define OFF_BETA  104
#define OFF_G     105

#define EPSV 1e-12f

// ---------------- device-global scratch ----------------
__device__ float g_Wt[PARTW * COMBP];        // transposed padded weights [j][k]
__device__ float g_bias[PARTW];
__device__ float g_comb[BATCH * COMBP];
__device__ float g_part[KSPLIT * BATCH * PARTW];
__device__ float g_upd_unused;               // (kept out: upd lives in smem via partials)
__device__ float g_wt[BATCH * NH * NA];
__device__ float g_wtdyn[BATCH * NH * NA];
__device__ float g_mem[BATCH * MSZ * NA];

__device__ __forceinline__ float sigm(float x) { return 1.0f / (1.0f + __expf(-x)); }
__device__ __forceinline__ float splus(float x) {
    return fmaxf(x, 0.0f) + log1pf(__expf(-fabsf(x)));
}

// ---------------- weight repack: g_Wt[j][k] = W*[k][j], zero pads, bias ----------------
__global__ void pack_kernel(const float* __restrict__ Wo, const float* __restrict__ bo,
                            const float* __restrict__ Ws, const float* __restrict__ bs,
                            const float* __restrict__ Wu, const float* __restrict__ bu) {
    int idx = blockIdx.x * 256 + threadIdx.x;
    if (idx < PARTW * COMBP) {
        int j = idx >> 10;
        int k = idx & (COMBP - 1);
        float v = 0.0f;
        if (k < COMBD && j < OUTD) {
            if (j < DB)            v = Wo[k * DB + j];
            else if (j < DB + SU)  v = Ws[k * SU + (j - DB)];
            else                   v = Wu[k * UPDD + (j - DB - SU)];
        }
        g_Wt[idx] = v;
    }
    if (idx < PARTW) {
        g_bias[idx] = (idx >= OUTD) ? 0.0f
                    : (idx < DB) ? bo[idx]
                    : (idx < DB + SU) ? bs[idx - DB]
                    : bu[idx - DB - SU];
    }
}

// ---------------- init: reset carry + build comb_0 ----------------
__global__ void init_kernel(const float* __restrict__ x) {
    int b = blockIdx.x, tid = threadIdx.x;
    for (int i = tid; i < NH * NA; i += 256) {
        float v = ((i & (NA - 1)) == 0) ? 1.0f : 0.0f;
        g_wt[b * NH * NA + i]    = v;
        g_wtdyn[b * NH * NA + i] = v;
    }
    for (int i = tid; i < MSZ * NA; i += 256) g_mem[b * MSZ * NA + i] = 0.01f;
    for (int i = tid; i < COMBP; i += 256) {
        float v;
        if (i < INDIM)            v = x[((size_t)b * TSEQ + 0) * INDIM + i];
        else if (i < INDIM + SU)  v = 1.0f;
        else if (i < COMBD)       v = 0.01f;
        else                      v = 0.0f;
        g_comb[b * COMBP + i] = v;
    }
}

// ---------------- GEMM: partial[ks][row][col] over K-chunk ----------------
// grid (NCB, KSPLIT), 256 threads. Thread = 4 rows x 2 cols.
__global__ void __launch_bounds__(256) gemm_kernel() {
    __shared__ float cS[64][KSUB + 4];   // stride 68
    __shared__ float wS[CB][KSUB + 4];

    int tid = threadIdx.x;
    int cb = blockIdx.x, ks = blockIdx.y;
    int j0 = cb * CB;
    int k0 = ks * KCH;
    int rq = tid >> 4;          // 0..15 -> rows 4rq..4rq+3
    int cp = tid & 15;          // cols cp, cp+16
    int r0 = rq * 4;

    float acc00 = 0.f, acc01 = 0.f, acc10 = 0.f, acc11 = 0.f;
    float acc20 = 0.f, acc21 = 0.f, acc30 = 0.f, acc31 = 0.f;

    float4 cP[4], wP[2];

    // prefetch subchunk 0
    {
        int kc = k0;
        #pragma unroll
        for (int s = 0; s < 4; s++) {
            int p = tid + s * 256;                 // 1024 float4 (64 rows x 16)
            int r = p >> 4, k4 = p & 15;
            cP[s] = *(const float4*)&g_comb[r * COMBP + kc + 4 * k4];
        }
        #pragma unroll
        for (int s = 0; s < 2; s++) {
            int p = tid + s * 256;                 // 512 float4 (32 cols x 16)
            int jj = p >> 4, k4 = p & 15;
            wP[s] = *(const float4*)&g_Wt[(size_t)(j0 + jj) * COMBP + kc + 4 * k4];
        }
    }

    #pragma unroll 1
    for (int sub = 0; sub < KCH / KSUB; sub++) {
        // commit prefetched subchunk
        #pragma unroll
        for (int s = 0; s < 4; s++) {
            int p = tid + s * 256;
            int r = p >> 4, k4 = p & 15;
            *(float4*)&cS[r][4 * k4] = cP[s];
        }
        #pragma unroll
        for (int s = 0; s < 2; s++) {
            int p = tid + s * 256;
            int jj = p >> 4, k4 = p & 15;
            *(float4*)&wS[jj][4 * k4] = wP[s];
        }
        __syncthreads();

        // prefetch next subchunk
        if (sub < KCH / KSUB - 1) {
            int kc = k0 + (sub + 1) * KSUB;
            #pragma unroll
            for (int s = 0; s < 4; s++) {
                int p = tid + s * 256;
                int r = p >> 4, k4 = p & 15;
                cP[s] = *(const float4*)&g_comb[r * COMBP + kc + 4 * k4];
            }
            #pragma unroll
            for (int s = 0; s < 2; s++) {
                int p = tid + s * 256;
                int jj = p >> 4, k4 = p & 15;
                wP[s] = *(const float4*)&g_Wt[(size_t)(j0 + jj) * COMBP + kc + 4 * k4];
            }
        }

        #pragma unroll 8
        for (int kk = 0; kk < KSUB; kk += 4) {
            float4 w0 = *(const float4*)&wS[cp][kk];
            float4 w1 = *(const float4*)&wS[cp + 16][kk];
            float4 a0 = *(const float4*)&cS[r0 + 0][kk];
            float4 a1 = *(const float4*)&cS[r0 + 1][kk];
            float4 a2 = *(const float4*)&cS[r0 + 2][kk];
            float4 a3 = *(const float4*)&cS[r0 + 3][kk];
            acc00 = fmaf(a0.x, w0.x, acc00); acc00 = fmaf(a0.y, w0.y, acc00);
            acc00 = fmaf(a0.z, w0.z, acc00); acc00 = fmaf(a0.w, w0.w, acc00);
            acc01 = fmaf(a0.x, w1.x, acc01); acc01 = fmaf(a0.y, w1.y, acc01);
            acc01 = fmaf(a0.z, w1.z, acc01); acc01 = fmaf(a0.w, w1.w, acc01);
            acc10 = fmaf(a1.x, w0.x, acc10); acc10 = fmaf(a1.y, w0.y, acc10);
            acc10 = fmaf(a1.z, w0.z, acc10); acc10 = fmaf(a1.w, w0.w, acc10);
            acc11 = fmaf(a1.x, w1.x, acc11); acc11 = fmaf(a1.y, w1.y, acc11);
            acc11 = fmaf(a1.z, w1.z, acc11); acc11 = fmaf(a1.w, w1.w, acc11);
            acc20 = fmaf(a2.x, w0.x, acc20); acc20 = fmaf(a2.y, w0.y, acc20);
            acc20 = fmaf(a2.z, w0.z, acc20); acc20 = fmaf(a2.w, w0.w, acc20);
            acc21 = fmaf(a2.x, w1.x, acc21); acc21 = fmaf(a2.y, w1.y, acc21);
            acc21 = fmaf(a2.z, w1.z, acc21); acc21 = fmaf(a2.w, w1.w, acc21);
            acc30 = fmaf(a3.x, w0.x, acc30); acc30 = fmaf(a3.y, w0.y, acc30);
            acc30 = fmaf(a3.z, w0.z, acc30); acc30 = fmaf(a3.w, w0.w, acc30);
            acc31 = fmaf(a3.x, w1.x, acc31); acc31 = fmaf(a3.y, w1.y, acc31);
            acc31 = fmaf(a3.z, w1.z, acc31); acc31 = fmaf(a3.w, w1.w, acc31);
        }
        __syncthreads();
    }

    float* pp = &g_part[(ks * BATCH) * PARTW];
    pp[(r0 + 0) * PARTW + j0 + cp]      = acc00;
    pp[(r0 + 0) * PARTW + j0 + cp + 16] = acc01;
    pp[(r0 + 1) * PARTW + j0 + cp]      = acc10;
    pp[(r0 + 1) * PARTW + j0 + cp + 16] = acc11;
    pp[(r0 + 2) * PARTW + j0 + cp]      = acc20;
    pp[(r0 + 2) * PARTW + j0 + cp + 16] = acc21;
    pp[(r0 + 3) * PARTW + j0 + cp]      = acc30;
    pp[(r0 + 3) * PARTW + j0 + cp + 16] = acc31;
}

// ---------------- update: combine partials + DWM cell; grid=64, 1024 thr ----------------
#define MPAD (NA + 4)    // 260: float4-friendly padded stride
__global__ void __launch_bounds__(1024) update_kernel(const float* __restrict__ x,
                                                      float* __restrict__ dout, int t) {
    __shared__ float memS[MSZ][MPAD];
    __shared__ float wtS[NH][NA];
    __shared__ float wgS[NH][NA];
    __shared__ float upS[UPDD];
    __shared__ float4 pE4[MSZ], pA4[MSZ];     // per-m, 4 heads packed
    __shared__ float pK[NH][MSZ];
    __shared__ float pS[NH][3], pJ[NH][3];
    __shared__ float pJd[NH], pGam[NH], pBeta[NH], pG[NH];
    __shared__ float readS[NH * MSZ];
    __shared__ float redA[NH][8], redB[NH][8];

    int b = blockIdx.x, tid = threadIdx.x;
    int h = tid >> 8, n = tid & 255;
    int wih = (tid >> 5) & 7, lane = tid & 31;

    // prefetch wtdyn (RMW later, off the critical path)
    float dynOld = g_wtdyn[b * NH * NA + tid];

    // ---- phase 1: load mem (f4) + wt; combine partials + route ----
    #pragma unroll
    for (int s = 0; s < 2; s++) {
        int p = tid + s * 1024;            // f4 index, 2048 total
        int m = p >> 6, nn4 = p & 63;
        float4 v = ((const float4*)&g_mem[b * MSZ * NA])[p];
        *(float4*)&memS[m][4 * nn4] = v;
    }
    wtS[h][n] = g_wt[b * NH * NA + tid];

    if (tid < 298) {
        const float4* p0 = (const float4*)&g_part[(0 * BATCH + b) * PARTW];
        const float4* p1 = (const float4*)&g_part[(1 * BATCH + b) * PARTW];
        const float4* p2 = (const float4*)&g_part[(2 * BATCH + b) * PARTW];
        const float4* p3 = (const float4*)&g_part[(3 * BATCH + b) * PARTW];
        float4 v0 = p0[tid], v1 = p1[tid], v2 = p2[tid], v3 = p3[tid];
        float4 bi = ((const float4*)g_bias)[tid];
        float r0v = v0.x + v1.x + v2.x + v3.x + bi.x;
        float r1v = v0.y + v1.y + v2.y + v3.y + bi.y;
        float r2v = v0.z + v1.z + v2.z + v3.z + bi.z;
        float r3v = v0.w + v1.w + v2.w + v3.w + bi.w;
        if (tid < 64) {                    // cols [0,256): out -> dout
            float4 o = make_float4(sigm(r0v), sigm(r1v), sigm(r2v), sigm(r3v));
            *(float4*)&dout[((size_t)b * TSEQ + t) * DB + 4 * tid] = o;
        } else if (tid < 192) {            // cols [256,768): state -> comb directly
            float4 o = make_float4(sigm(r0v), sigm(r1v), sigm(r2v), sigm(r3v));
            *(float4*)&g_comb[b * COMBP + INDIM + 4 * tid - 256] = o;
        } else {                           // cols [768,1192): interface params
            int u = 4 * tid - 768;
            upS[u] = r0v; upS[u + 1] = r1v; upS[u + 2] = r2v; upS[u + 3] = r3v;
        }
    }
    __syncthreads();

    // ---- phase 2: parse interface params ----
    if (tid < NH * 32) {
        int hh = tid >> 5, m = tid & 31;
        const float* up = &upS[hh * HP];
        float ev = sigm(up[OFF_ER + m]);
        float av = up[OFF_AD + m];
        ((float*)&pE4[m])[hh] = ev;
        ((float*)&pA4[m])[hh] = av;
        float kt = tanhf(up[OFF_K + m]);
        float ssk = kt * kt;
        #pragma unroll
        for (int o = 16; o; o >>= 1) ssk += __shfl_xor_sync(0xffffffffu, ssk, o);
        pK[hh][m] = kt / (sqrtf(ssk) + EPSV);
        if (m == 0) {
            float s0 = splus(up[OFF_S + 0]), s1 = splus(up[OFF_S + 1]), s2 = splus(up[OFF_S + 2]);
            float mx = fmaxf(s0, fmaxf(s1, s2));
            float e0 = __expf(s0 - mx), e1 = __expf(s1 - mx), e2 = __expf(s2 - mx);
            float inv = 1.0f / (e0 + e1 + e2);
            pS[hh][0] = e0 * inv; pS[hh][1] = e1 * inv; pS[hh][2] = e2 * inv;
            float j0r = up[OFF_J + 0], j1r = up[OFF_J + 1], j2r = up[OFF_J + 2];
            float jm = fmaxf(j0r, fmaxf(j1r, j2r));
            float f0 = __expf(j0r - jm), f1 = __expf(j1r - jm), f2 = __expf(j2r - jm);
            float jinv = 1.0f / (f0 + f1 + f2);
            pJ[hh][0] = f0 * jinv; pJ[hh][1] = f1 * jinv; pJ[hh][2] = f2 * jinv;
            pJd[hh]   = sigm(up[OFF_JD]);
            pGam[hh]  = 1.0f + splus(up[OFF_GAM]);
            pBeta[hh] = splus(up[OFF_BETA]);
            pG[hh]    = sigm(up[OFF_G]);
        }
    }
    __syncthreads();

    // ---- phase 3: memory write (erase, add); write back f4 ----
    #pragma unroll
    for (int s = 0; s < 2; s++) {
        int p = tid + s * 1024;
        int m = p >> 6, nn4 = p & 63;
        float4 mv = *(const float4*)&memS[m][4 * nn4];
        float4 e4 = pE4[m], a4 = pA4[m];
        float4 w0 = *(const float4*)&wtS[0][4 * nn4];
        float4 w1 = *(const float4*)&wtS[1][4 * nn4];
        float4 w2 = *(const float4*)&wtS[2][4 * nn4];
        float4 w3 = *(const float4*)&wtS[3][4 * nn4];
        #pragma unroll
        for (int i = 0; i < 4; i++) {
            float vv = (&mv.x)[i];
            float ww0 = (&w0.x)[i], ww1 = (&w1.x)[i], ww2 = (&w2.x)[i], ww3 = (&w3.x)[i];
            float prod = (1.0f - e4.x * ww0) * (1.0f - e4.y * ww1)
                       * (1.0f - e4.z * ww2) * (1.0f - e4.w * ww3);
            float addv = a4.x * ww0 + a4.y * ww1 + a4.z * ww2 + a4.w * ww3;
            (&mv.x)[i] = vv * prod + addv;
        }
        *(float4*)&memS[m][4 * nn4] = mv;
        ((float4*)&g_mem[b * MSZ * NA])[p] = mv;
    }
    __syncthreads();

    // ---- phase 4: norm + content score + per-head softmax, gate ----
    float ss = 0.0f, sc = 0.0f;
    #pragma unroll
    for (int m = 0; m < MSZ; m++) {
        float v = memS[m][n];
        ss = fmaf(v, v, ss);
        sc = fmaf(pK[h][m], v, sc);
    }
    sc = sc * pBeta[h] / (sqrtf(ss) + EPSV);

    float mv = sc;
    #pragma unroll
    for (int o = 16; o; o >>= 1) mv = fmaxf(mv, __shfl_xor_sync(0xffffffffu, mv, o));
    if (lane == 0) redA[h][wih] = mv;
    __syncthreads();
    mv = redA[h][0];
    #pragma unroll
    for (int w = 1; w < 8; w++) mv = fmaxf(mv, redA[h][w]);
    float e = __expf(sc - mv);
    float sv = e;
    #pragma unroll
    for (int o = 16; o; o >>= 1) sv += __shfl_xor_sync(0xffffffffu, sv, o);
    if (lane == 0) redB[h][wih] = sv;
    __syncthreads();
    float tot = redB[h][0];
    #pragma unroll
    for (int w = 1; w < 8; w++) tot += redB[h][w];
    float wc = e / tot;
    float g = pG[h];
    wgS[h][n] = fmaf(g, wc - wtS[h][n], wtS[h][n]);
    __syncthreads();

    // ---- phase 5: shift, sharpen, snapshot, jump ----
    float ws = pS[h][0] * wgS[h][(n + NA - 1) & (NA - 1)]
             + pS[h][1] * wgS[h][n]
             + pS[h][2] * wgS[h][(n + 1) & (NA - 1)];
    ws = __expf(pGam[h] * __logf(ws + EPSV));
    float sv2 = ws;
    #pragma unroll
    for (int o = 16; o; o >>= 1) sv2 += __shfl_xor_sync(0xffffffffu, sv2, o);
    if (lane == 0) redA[h][wih] = sv2;
    __syncthreads();
    float tot2 = redA[h][0];
    #pragma unroll
    for (int w = 1; w < 8; w++) tot2 += redA[h][w];
    ws /= tot2;

    int gi = b * NH * NA + tid;
    float jd = pJd[h];
    float dynNew = fmaf(jd, ws - dynOld, dynOld);
    g_wtdyn[gi] = dynNew;
    float wnew = pJ[h][0] * ws + pJ[h][1] * dynNew + ((n == 0) ? pJ[h][2] : 0.0f);
    g_wt[gi] = wnew;
    wtS[h][n] = wnew;
    __syncthreads();

    // ---- phase 6: read[h][m] = sum_n wt_new[h][n] * mem[m][n] ----
    if (tid < 512) {
        int hh = tid >> 7;
        int m  = (tid >> 2) & 31;
        int q  = tid & 3;
        float acc = 0.0f;
        #pragma unroll
        for (int i = 0; i < 64; i++) {
            int nn = q * 64 + ((i + 8 * q) & 63);
            acc = fmaf(wtS[hh][nn], memS[m][nn], acc);
        }
        acc += __shfl_down_sync(0xffffffffu, acc, 2, 4);
        acc += __shfl_down_sync(0xffffffffu, acc, 1, 4);
        if (q == 0) readS[hh * MSZ + m] = acc;
    }
    __syncthreads();

    // ---- phase 7: write read + x_{t+1} into comb (state already written) ----
    if (tid < 32) {
        *(float4*)&g_comb[b * COMBP + INDIM + SU + 4 * tid] = *(const float4*)&readS[4 * tid];
    } else if (tid >= 64 && tid < 130) {
        int i4 = tid - 64;  // 66 float4 = 264 floats of x
        float4 xv = *(const float4*)&x[((size_t)b * TSEQ + (t + 1)) * INDIM + 4 * i4];
        *(float4*)&g_comb[b * COMBP + 4 * i4] = xv;
    }
}

// ---------------- final out at t=255 ----------------
__global__ void __launch_bounds__(256) outfin_kernel(float* __restrict__ dout) {
    int b = blockIdx.x, j = threadIdx.x;   // j < 256 = DB
    float v = g_part[(0 * BATCH + b) * PARTW + j]
            + g_part[(1 * BATCH + b) * PARTW + j]
            + g_part[(2 * BATCH + b) * PARTW + j]
            + g_part[(3 * BATCH + b) * PARTW + j]
            + g_bias[j];
    dout[((size_t)b * TSEQ + (TSEQ - 1)) * DB + j] = sigm(v);
}

// ---------------- host ----------------
extern "C" void kernel_launch(void* const* d_in, const int* in_sizes, int n_in,
                              void* d_out, int out_size) {
    const float* x  = (const float*)d_in[0];
    const float* Wo = (const float*)d_in[1];
    const float* bo = (const float*)d_in[2];
    const float* Ws = (const float*)d_in[3];
    const float* bs = (const float*)d_in[4];
    const float* Wu = (const float*)d_in[5];
    const float* bu = (const float*)d_in[6];
    float* out = (float*)d_out;

    pack_kernel<<<(PARTW * COMBP + 255) / 256, 256>>>(Wo, bo, Ws, bs, Wu, bu);
    init_kernel<<<BATCH, 256>>>(x);
    for (int t = 0; t < TSEQ; t++) {
        gemm_kernel<<<dim3(NCB, KSPLIT), 256>>>();
        if (t < TSEQ - 1) update_kernel<<<BATCH, 1024>>>(x, out, t);
    }
    outfin_kernel<<<BATCH, 256>>>(out);
}